// round 7
// baseline (speedup 1.0000x reference)
#include <cuda_runtime.h>
#include <cstdint>

#define BB 16
#define NN 2000
#define EE 8000
#define DD 64
#define XROWS 10000
#define E2MAX 16000

// ---------------- scratch (device globals) ----------------
__device__ __align__(16) float g_h [BB * NN * DD];
__device__ __align__(16) float g_A [BB * NN * DD];
__device__ __align__(16) float g_C [BB * NN * DD];
__device__ __align__(16) float g_Bf[BB * EE * DD];
__device__ __align__(16) float g_M [DD * DD];     // W_edge@W2
__device__ __align__(16) float g_WA[DD * DD];     // W_node@W1
__device__ __align__(16) float g_WC[DD * DD];     // W_node@W3
__device__ __align__(16) float g_bA[DD];
__device__ __align__(16) float g_bC[DD];
__device__ float g_expl[BB * E2MAX];
__device__ float g_psum[BB * (E2MAX / 16)];
__device__ int   g_start[NN + 1];

__device__ __forceinline__ uint32_t f2tf(float f) {
    uint32_t r; asm("cvt.rna.tf32.f32 %0, %1;" : "=r"(r) : "f"(f)); return r;
}

// ---------------- prep: 3 mm64 + bias + ranges, one kernel ----------------
__device__ void mm64_dev(const float* __restrict__ A, const float* __restrict__ B,
                         float* __restrict__ O)
{
    __shared__ float sa[4096], sb[4096];
    int tid = threadIdx.x;
    for (int i = tid; i < 4096; i += 256) { sa[i] = A[i]; sb[i] = B[i]; }
    __syncthreads();
    for (int o = tid; o < 4096; o += 256) {
        int i = o >> 6, j = o & 63;
        float s = 0.f;
        #pragma unroll 16
        for (int k = 0; k < 64; k++) s += sa[i * 64 + k] * sb[k * 64 + j];
        O[o] = s;
    }
}

__global__ void prep_kernel(const float* __restrict__ W_edge,
                            const float* __restrict__ W_node,
                            const float* __restrict__ b_node,
                            const float* __restrict__ W_comb,
                            const int* __restrict__ src, int E2)
{
    int blk = blockIdx.x, tid = threadIdx.x;
    if (blk == 0)      mm64_dev(W_edge, W_comb + 64 * 64,  g_M);
    else if (blk == 1) mm64_dev(W_node, W_comb,            g_WA);
    else if (blk == 2) mm64_dev(W_node, W_comb + 128 * 64, g_WC);
    else if (blk == 3) {
        if (tid < 128) {
            int c = tid & 63;
            const float* W = (tid < 64) ? W_comb : (W_comb + 128 * 64);
            float s = 0.f;
            #pragma unroll 16
            for (int k = 0; k < 64; k++) s += b_node[k] * W[k * 64 + c];
            if (tid < 64) g_bA[c] = s; else g_bC[c] = s;
        }
    } else {
        for (int n = tid; n <= NN; n += 256) {
            int lo = 0, hi = E2;
            while (lo < hi) { int m = (lo + hi) >> 1; if (src[m] < n) lo = m + 1; else hi = m; }
            g_start[n] = lo;
        }
    }
}

// ---------------- tf32 mma.sync GEMM: 128x64 tile, K=64, vectorized frags ----
// A smem: k-permuted within 8-blocks so (t, t+4) adjacent -> LDS.64 pairs.
//   word(r, k) = r*XS_S + (k>>3)*8 + 2*(k&3) + ((k&7)>>2)
// W smem: n-permuted so a thread's 8 nt values are contiguous -> LDS.128.
//   word(k, n) = k*XS_S + (n&7)*8 + (n>>3)
#define XS_S 68
#define SMEM_GEMM ((128 * XS_S + 64 * XS_S) * 4)   // 52224 bytes

__global__ void __launch_bounds__(256)
gemm_mma_kernel(const float* __restrict__ X,
                const float* __restrict__ W_node, const float* __restrict__ b_node,
                int bidBase)
{
    extern __shared__ uint32_t sm[];
    uint32_t* xs = sm;               // [128][68]
    uint32_t* ws = sm + 128 * XS_S;  // [64][68]

    int bid = blockIdx.x + bidBase, set, rb;
    if (bid < 750) { set = bid / 250; rb = bid - set * 250; }
    else           { set = 3;         rb = bid - 750; }
    const float* Wp; const float* bp; float* Yp;
    if (set == 0)      { Wp = W_node; bp = b_node; Yp = g_h; }
    else if (set == 1) { Wp = g_WA;   bp = g_bA;   Yp = g_A; }
    else if (set == 2) { Wp = g_WC;   bp = g_bC;   Yp = g_C; }
    else               { Wp = g_M;    bp = nullptr; Yp = g_Bf; }
    const int bR  = (set < 3) ? NN : EE;
    const int off = (set < 3) ? EE : 0;
    const int rowBase = rb * 128;

    const int tid = threadIdx.x;

    // stage X tile (128x64) -> tf32, k-permuted
    #pragma unroll
    for (int i = 0; i < 8; i++) {
        int idx = tid + i * 256;        // float4 slots
        int r   = idx >> 4;
        int c4  = idx & 15;
        int gr  = rowBase + r;
        int sb  = gr / bR;
        long srow = (long)sb * XROWS + off + (gr - sb * bR);
        float4 v = ((const float4*)X)[srow * 16 + c4];
        int base = r * XS_S + (c4 >> 1) * 8 + (c4 & 1);   // k=4*c4+j -> +2j
        xs[base + 0] = f2tf(v.x);
        xs[base + 2] = f2tf(v.y);
        xs[base + 4] = f2tf(v.z);
        xs[base + 6] = f2tf(v.w);
    }
    // stage W (64x64 k-major) -> tf32, n-permuted
    #pragma unroll
    for (int i = 0; i < 4; i++) {
        int idx = tid + i * 256;
        int k   = idx >> 4;
        int c4  = idx & 15;
        float4 v = ((const float4*)Wp)[idx];
        int base = k * XS_S + (c4 & 1) * 32 + (c4 >> 1);  // n=4*c4+j -> +8j
        ws[base + 0]  = f2tf(v.x);
        ws[base + 8]  = f2tf(v.y);
        ws[base + 16] = f2tf(v.z);
        ws[base + 24] = f2tf(v.w);
    }
    __syncthreads();

    const int warp = tid >> 5, lane = tid & 31;
    const int g = lane >> 2, t = lane & 3;
    const int r0 = warp * 16;

    float acc[8][4];
    #pragma unroll
    for (int nt = 0; nt < 8; nt++)
        #pragma unroll
        for (int j = 0; j < 4; j++) acc[nt][j] = 0.f;

    #pragma unroll
    for (int ks = 0; ks < 8; ks++) {
        uint2 apair0 = *(const uint2*)&xs[(r0 + g)     * XS_S + ks * 8 + 2 * t]; // a0,a2
        uint2 apair1 = *(const uint2*)&xs[(r0 + g + 8) * XS_S + ks * 8 + 2 * t]; // a1,a3
        const uint32_t* brow0 = ws + (ks * 8 + t)     * XS_S + g * 8;
        const uint32_t* brow1 = ws + (ks * 8 + t + 4) * XS_S + g * 8;
        uint4 B0a = *(const uint4*)brow0;
        uint4 B0b = *(const uint4*)(brow0 + 4);
        uint4 B1a = *(const uint4*)brow1;
        uint4 B1b = *(const uint4*)(brow1 + 4);
        uint32_t b0v[8] = {B0a.x, B0a.y, B0a.z, B0a.w, B0b.x, B0b.y, B0b.z, B0b.w};
        uint32_t b1v[8] = {B1a.x, B1a.y, B1a.z, B1a.w, B1b.x, B1b.y, B1b.z, B1b.w};
        #pragma unroll
        for (int nt = 0; nt < 8; nt++) {
            asm volatile(
                "mma.sync.aligned.m16n8k8.row.col.f32.tf32.tf32.f32 "
                "{%0,%1,%2,%3}, {%4,%5,%6,%7}, {%8,%9}, {%0,%1,%2,%3};"
                : "+f"(acc[nt][0]), "+f"(acc[nt][1]), "+f"(acc[nt][2]), "+f"(acc[nt][3])
                : "r"(apair0.x), "r"(apair1.x), "r"(apair0.y), "r"(apair1.y),
                  "r"(b0v[nt]), "r"(b1v[nt]));
        }
    }

    // epilogue: lane holds rows {r0+g, r0+g+8}, cols {nt*8+2t, nt*8+2t+1}
    long row0 = rowBase + r0 + g;
    long row1 = row0 + 8;
    #pragma unroll
    for (int nt = 0; nt < 8; nt++) {
        int c = nt * 8 + 2 * t;
        float bx = bp ? __ldg(bp + c)     : 0.f;
        float by = bp ? __ldg(bp + c + 1) : 0.f;
        ((float2*)(Yp + row0 * 64 + c))[0] = make_float2(acc[nt][0] + bx, acc[nt][1] + by);
        ((float2*)(Yp + row1 * 64 + c))[0] = make_float2(acc[nt][2] + bx, acc[nt][3] + by);
    }
}

// ---------------- edge: combine + lrelu + exp(logit) + partial sums ----------------
__global__ void edge_kernel(const float* __restrict__ b_comb,
                            const float* __restrict__ w_attn,
                            const int* __restrict__ src,
                            const int* __restrict__ dst,
                            const int* __restrict__ eidx,
                            float* __restrict__ out, int E2)
{
    __shared__ float wred[16];
    int warp = threadIdx.x >> 5, lane = threadIdx.x & 31;
    int gw = blockIdx.x * 16 + warp;
    int b = gw / E2;
    int e = gw - b * E2;
    int s = src[e], t = dst[e], q = eidx[e];

    float2 va = ((const float2*)(g_A  + ((long)b * NN + s) * DD))[lane];
    float2 vf = ((const float2*)(g_Bf + ((long)b * EE + q) * DD))[lane];
    float2 vc = ((const float2*)(g_C  + ((long)b * NN + t) * DD))[lane];
    float2 vb = ((const float2*)b_comb)[lane];

    float v0 = va.x + vf.x + vc.x + vb.x;
    float v1 = va.y + vf.y + vc.y + vb.y;
    v0 = v0 > 0.f ? v0 : 0.01f * v0;
    v1 = v1 > 0.f ? v1 : 0.01f * v1;

    ((float2*)(out + ((long)b * (E2 + NN) + e) * DD))[lane] = make_float2(v0, v1);

    float2 w = ((const float2*)w_attn)[lane];
    float dot = v0 * w.x + v1 * w.y;
    #pragma unroll
    for (int o = 16; o; o >>= 1) dot += __shfl_xor_sync(0xffffffffu, dot, o);

    float ev = expf(dot);
    if (lane == 0) { g_expl[gw] = ev; wred[warp] = ev; }
    __syncthreads();
    if (threadIdx.x < 16) {
        float v = wred[threadIdx.x];
        #pragma unroll
        for (int o = 8; o; o >>= 1) v += __shfl_xor_sync(0xffffu, v, o);
        if (threadIdx.x == 0) g_psum[blockIdx.x] = v;
    }
}

// ---------------- aggregate (sum fused in): h_out = seg-sum alpha*h[dst] ----
__global__ void aggregate_kernel(const int* __restrict__ dst,
                                 float* __restrict__ out, int E2)
{
    __shared__ float red[256];
    __shared__ float s_inv;
    const int pb = E2 / 16;                 // edge-kernel blocks per batch
    int tid = threadIdx.x;
    int warp = tid >> 5, lane = tid & 31;
    int b = blockIdx.x / (NN / 8);          // 250 blocks per batch

    // block-level: 1/sum of this batch's partials
    float s = 0.f;
    for (int j = tid; j < pb; j += 256) s += g_psum[b * pb + j];
    red[tid] = s; __syncthreads();
    for (int st = 128; st > 0; st >>= 1) {
        if (tid < st) red[tid] += red[tid + st];
        __syncthreads();
    }
    if (tid == 0) s_inv = 1.0f / red[0];
    __syncthreads();

    int gw = blockIdx.x * 8 + warp;
    int n = gw - b * NN;
    int s0 = g_start[n], s1 = g_start[n + 1];
    float inv = s_inv;
    const float2* hb = (const float2*)(g_h + (long)b * NN * DD);
    const float*  ex = g_expl + (long)b * E2;
    float2 acc = make_float2(0.f, 0.f);
    for (int i = s0; i < s1; i++) {
        float a = ex[i] * inv;
        float2 hv = hb[(long)dst[i] * 32 + lane];
        acc.x += a * hv.x;
        acc.y += a * hv.y;
    }
    ((float2*)(out + ((long)b * (E2 + NN) + E2 + n) * DD))[lane] = acc;
}

// ---------------- launch ----------------
extern "C" void kernel_launch(void* const* d_in, const int* in_sizes, int n_in,
                              void* d_out, int out_size)
{
    const float* x      = (const float*)d_in[0];
    const float* W_edge = (const float*)d_in[1];
    const float* W_node = (const float*)d_in[2];
    const float* b_node = (const float*)d_in[3];
    const float* W_comb = (const float*)d_in[4];
    const float* b_comb = (const float*)d_in[5];
    const float* w_attn = (const float*)d_in[6];
    const int*   src    = (const int*)d_in[7];
    const int*   dst    = (const int*)d_in[8];
    const int*   eidx   = (const int*)d_in[9];
    const int    E2     = in_sizes[7];   // 16000
    float* out = (float*)d_out;

    cudaFuncSetAttribute(gemm_mma_kernel, cudaFuncAttributeMaxDynamicSharedMemorySize, SMEM_GEMM);

    prep_kernel     <<<5, 256>>>(W_edge, W_node, b_node, W_comb, src, E2);   // idx 0
    gemm_mma_kernel <<<750,  256, SMEM_GEMM>>>(x, W_node, b_node, 0);        // idx 1 (h,A,C)
    gemm_mma_kernel <<<1000, 256, SMEM_GEMM>>>(x, W_node, b_node, 750);      // idx 2 (Bf)
    edge_kernel     <<<BB * E2 / 16, 512>>>(b_comb, w_attn, src, dst, eidx, out, E2); // idx 3 (profiled)
    aggregate_kernel<<<BB * NN / 8, 256>>>(dst, out, E2);                    // idx 4
}

// round 8
// speedup vs baseline: 1.2998x; 1.2998x over previous
#include <cuda_runtime.h>
#include <cstdint>

#define BB 16
#define NN 2000
#define EE 8000
#define DD 64
#define XROWS 10000
#define E2C 16000

// ---------------- scratch (device globals) ----------------
__device__ __align__(16) float g_h [BB * NN * DD];
__device__ __align__(16) float g_A [BB * NN * DD];
__device__ __align__(16) float g_C [BB * NN * DD];
__device__ __align__(16) float g_Bf[BB * EE * DD];
__device__ __align__(16) float g_M [DD * DD];     // W_edge@W2
__device__ __align__(16) float g_WA[DD * DD];     // W_node@W1
__device__ __align__(16) float g_WC[DD * DD];     // W_node@W3
__device__ __align__(16) float g_bA[DD];          // b_node@W1 + b_comb
__device__ __align__(16) float g_bC[DD];          // b_node@W3
__device__ float g_expl[BB * E2C];
__device__ float g_psum[BB * (E2C / 16)];
__device__ int   g_start[NN + 1];

__device__ __forceinline__ uint32_t f2tf(float f) {
    uint32_t r; asm("cvt.rna.tf32.f32 %0, %1;" : "=r"(r) : "f"(f)); return r;
}

// ---------------- prep: 3 mm64 + bias + ranges, one kernel ----------------
__device__ void mm64_dev(const float* __restrict__ A, const float* __restrict__ B,
                         float* __restrict__ O)
{
    __shared__ float sa[4096], sb[4096];
    int tid = threadIdx.x;
    for (int i = tid; i < 4096; i += 256) { sa[i] = A[i]; sb[i] = B[i]; }
    __syncthreads();
    for (int o = tid; o < 4096; o += 256) {
        int i = o >> 6, j = o & 63;
        float s = 0.f;
        #pragma unroll 16
        for (int k = 0; k < 64; k++) s += sa[i * 64 + k] * sb[k * 64 + j];
        O[o] = s;
    }
}

__global__ void prep_kernel(const float* __restrict__ W_edge,
                            const float* __restrict__ W_node,
                            const float* __restrict__ b_node,
                            const float* __restrict__ W_comb,
                            const float* __restrict__ b_comb,
                            const int* __restrict__ src)
{
    int blk = blockIdx.x, tid = threadIdx.x;
    if (blk == 0)      mm64_dev(W_edge, W_comb + 64 * 64,  g_M);
    else if (blk == 1) mm64_dev(W_node, W_comb,            g_WA);
    else if (blk == 2) mm64_dev(W_node, W_comb + 128 * 64, g_WC);
    else if (blk == 3) {
        if (tid < 128) {
            int c = tid & 63;
            const float* W = (tid < 64) ? W_comb : (W_comb + 128 * 64);
            float s = 0.f;
            #pragma unroll 16
            for (int k = 0; k < 64; k++) s += b_node[k] * W[k * 64 + c];
            if (tid < 64) g_bA[c] = s + b_comb[c];   // fold b_comb here
            else          g_bC[c] = s;
        }
    } else {
        for (int n = tid; n <= NN; n += 256) {
            int lo = 0, hi = E2C;
            while (lo < hi) { int m = (lo + hi) >> 1; if (src[m] < n) lo = m + 1; else hi = m; }
            g_start[n] = lo;
        }
    }
}

// ---------------- tf32 mma.sync GEMM: 128x64 tile, K=64, vectorized frags ----
#define XS_S 68
#define SMEM_GEMM ((128 * XS_S + 64 * XS_S) * 4)   // 52224 bytes

__global__ void __launch_bounds__(256)
gemm_mma_kernel(const float* __restrict__ X,
                const float* __restrict__ W_node, const float* __restrict__ b_node)
{
    extern __shared__ uint32_t sm[];
    uint32_t* xs = sm;               // [128][68]
    uint32_t* ws = sm + 128 * XS_S;  // [64][68]

    int bid = blockIdx.x, set, rb;
    if (bid < 750) { set = bid / 250; rb = bid - set * 250; }
    else           { set = 3;         rb = bid - 750; }
    const float* Wp; const float* bp; float* Yp;
    if (set == 0)      { Wp = W_node; bp = b_node; Yp = g_h; }
    else if (set == 1) { Wp = g_WA;   bp = g_bA;   Yp = g_A; }
    else if (set == 2) { Wp = g_WC;   bp = g_bC;   Yp = g_C; }
    else               { Wp = g_M;    bp = nullptr; Yp = g_Bf; }
    const int bR  = (set < 3) ? NN : EE;
    const int off = (set < 3) ? EE : 0;
    const int rowBase = rb * 128;

    const int tid = threadIdx.x;

    // stage X tile (128x64) -> tf32, k-permuted so (t, t+4) adjacent
    #pragma unroll
    for (int i = 0; i < 8; i++) {
        int idx = tid + i * 256;
        int r   = idx >> 4;
        int c4  = idx & 15;
        int gr  = rowBase + r;
        int sb  = gr / bR;
        long srow = (long)sb * XROWS + off + (gr - sb * bR);
        float4 v = ((const float4*)X)[srow * 16 + c4];
        int base = r * XS_S + (c4 >> 1) * 8 + (c4 & 1);
        xs[base + 0] = f2tf(v.x);
        xs[base + 2] = f2tf(v.y);
        xs[base + 4] = f2tf(v.z);
        xs[base + 6] = f2tf(v.w);
    }
    // stage W (64x64 k-major) -> tf32, n-permuted for LDS.128 per thread
    #pragma unroll
    for (int i = 0; i < 4; i++) {
        int idx = tid + i * 256;
        int k   = idx >> 4;
        int c4  = idx & 15;
        float4 v = ((const float4*)Wp)[idx];
        int base = k * XS_S + (c4 & 1) * 32 + (c4 >> 1);
        ws[base + 0]  = f2tf(v.x);
        ws[base + 8]  = f2tf(v.y);
        ws[base + 16] = f2tf(v.z);
        ws[base + 24] = f2tf(v.w);
    }
    __syncthreads();

    const int warp = tid >> 5, lane = tid & 31;
    const int g = lane >> 2, t = lane & 3;
    const int r0 = warp * 16;

    float acc[8][4];
    #pragma unroll
    for (int nt = 0; nt < 8; nt++)
        #pragma unroll
        for (int j = 0; j < 4; j++) acc[nt][j] = 0.f;

    #pragma unroll
    for (int ks = 0; ks < 8; ks++) {
        uint2 apair0 = *(const uint2*)&xs[(r0 + g)     * XS_S + ks * 8 + 2 * t];
        uint2 apair1 = *(const uint2*)&xs[(r0 + g + 8) * XS_S + ks * 8 + 2 * t];
        const uint32_t* brow0 = ws + (ks * 8 + t)     * XS_S + g * 8;
        const uint32_t* brow1 = ws + (ks * 8 + t + 4) * XS_S + g * 8;
        uint4 B0a = *(const uint4*)brow0;
        uint4 B0b = *(const uint4*)(brow0 + 4);
        uint4 B1a = *(const uint4*)brow1;
        uint4 B1b = *(const uint4*)(brow1 + 4);
        uint32_t b0v[8] = {B0a.x, B0a.y, B0a.z, B0a.w, B0b.x, B0b.y, B0b.z, B0b.w};
        uint32_t b1v[8] = {B1a.x, B1a.y, B1a.z, B1a.w, B1b.x, B1b.y, B1b.z, B1b.w};
        #pragma unroll
        for (int nt = 0; nt < 8; nt++) {
            asm volatile(
                "mma.sync.aligned.m16n8k8.row.col.f32.tf32.tf32.f32 "
                "{%0,%1,%2,%3}, {%4,%5,%6,%7}, {%8,%9}, {%0,%1,%2,%3};"
                : "+f"(acc[nt][0]), "+f"(acc[nt][1]), "+f"(acc[nt][2]), "+f"(acc[nt][3])
                : "r"(apair0.x), "r"(apair1.x), "r"(apair0.y), "r"(apair1.y),
                  "r"(b0v[nt]), "r"(b1v[nt]));
        }
    }

    long row0 = rowBase + r0 + g;
    long row1 = row0 + 8;
    #pragma unroll
    for (int nt = 0; nt < 8; nt++) {
        int c = nt * 8 + 2 * t;
        float bx = bp ? __ldg(bp + c)     : 0.f;
        float by = bp ? __ldg(bp + c + 1) : 0.f;
        ((float2*)(Yp + row0 * 64 + c))[0] = make_float2(acc[nt][0] + bx, acc[nt][1] + by);
        ((float2*)(Yp + row1 * 64 + c))[0] = make_float2(acc[nt][2] + bx, acc[nt][3] + by);
    }
}

// ---------------- edge: 16 lanes per edge, float4; 16 edges per 256-thr block ----
__global__ void __launch_bounds__(256)
edge_kernel(const float* __restrict__ w_attn,
            const int* __restrict__ src,
            const int* __restrict__ dst,
            const int* __restrict__ eidx,
            float* __restrict__ out)
{
    __shared__ float wred[16];
    const int tid    = threadIdx.x;
    const int slot   = tid >> 4;          // 0..15: edge slot in block
    const int lane16 = tid & 15;
    const int ge = blockIdx.x * 16 + slot;      // global (b,e)
    const int b  = ge / E2C;                    // const division -> mul
    const int e  = ge - b * E2C;
    const int s = src[e], t = dst[e], q = eidx[e];

    float4 a = ((const float4*)(g_A  + ((long)b * NN + s) * DD))[lane16];
    float4 f = ((const float4*)(g_Bf + ((long)b * EE + q) * DD))[lane16];
    float4 c = ((const float4*)(g_C  + ((long)b * NN + t) * DD))[lane16];

    float4 v;
    v.x = a.x + f.x + c.x;
    v.y = a.y + f.y + c.y;
    v.z = a.z + f.z + c.z;
    v.w = a.w + f.w + c.w;
    v.x = v.x > 0.f ? v.x : 0.01f * v.x;
    v.y = v.y > 0.f ? v.y : 0.01f * v.y;
    v.z = v.z > 0.f ? v.z : 0.01f * v.z;
    v.w = v.w > 0.f ? v.w : 0.01f * v.w;

    ((float4*)(out + ((long)b * (E2C + NN) + e) * DD))[lane16] = v;

    float4 w = ((const float4*)w_attn)[lane16];
    float dot = v.x * w.x + v.y * w.y + v.z * w.z + v.w * w.w;
    #pragma unroll
    for (int o = 8; o; o >>= 1) dot += __shfl_xor_sync(0xffffffffu, dot, o);

    float ev = __expf(dot);
    if (lane16 == 0) { g_expl[ge] = ev; wred[slot] = ev; }
    __syncthreads();
    if (tid < 16) {
        float x = wred[tid];
        #pragma unroll
        for (int o = 8; o; o >>= 1) x += __shfl_xor_sync(0xffffu, x, o);
        if (tid == 0) g_psum[blockIdx.x] = x;
    }
}

// ---------------- aggregate (sum fused): 16 lanes per node, float4 ----------------
// 256 threads = 16 node slots; 125 blocks per batch; grid = 16*125 = 2000
__global__ void __launch_bounds__(256)
aggregate_kernel(const int* __restrict__ dst, float* __restrict__ out)
{
    __shared__ float red[256];
    __shared__ float s_inv;
    const int pb = E2C / 16;               // 1000 edge-blocks per batch
    const int tid = threadIdx.x;
    const int slot = tid >> 4, lane16 = tid & 15;
    const int b = blockIdx.x / 125;

    float s = 0.f;
    for (int j = tid; j < pb; j += 256) s += g_psum[b * pb + j];
    red[tid] = s; __syncthreads();
    #pragma unroll
    for (int st = 128; st > 0; st >>= 1) {
        if (tid < st) red[tid] += red[tid + st];
        __syncthreads();
    }
    if (tid == 0) s_inv = 1.0f / red[0];
    __syncthreads();

    const int n = (blockIdx.x - b * 125) * 16 + slot;
    const int s0 = g_start[n], s1 = g_start[n + 1];
    const float inv = s_inv;
    const float4* hb = (const float4*)(g_h + (long)b * NN * DD);
    const float*  ex = g_expl + (long)b * E2C;
    float4 acc = make_float4(0.f, 0.f, 0.f, 0.f);
    for (int i = s0; i < s1; i++) {
        float al = ex[i] * inv;
        float4 hv = hb[(long)dst[i] * 16 + lane16];
        acc.x += al * hv.x;
        acc.y += al * hv.y;
        acc.z += al * hv.z;
        acc.w += al * hv.w;
    }
    ((float4*)(out + ((long)b * (E2C + NN) + E2C + n) * DD))[lane16] = acc;
}

// ---------------- launch ----------------
extern "C" void kernel_launch(void* const* d_in, const int* in_sizes, int n_in,
                              void* d_out, int out_size)
{
    const float* x      = (const float*)d_in[0];
    const float* W_edge = (const float*)d_in[1];
    const float* W_node = (const float*)d_in[2];
    const float* b_node = (const float*)d_in[3];
    const float* W_comb = (const float*)d_in[4];
    const float* b_comb = (const float*)d_in[5];
    const float* w_attn = (const float*)d_in[6];
    const int*   src    = (const int*)d_in[7];
    const int*   dst    = (const int*)d_in[8];
    const int*   eidx   = (const int*)d_in[9];
    float* out = (float*)d_out;

    cudaFuncSetAttribute(gemm_mma_kernel, cudaFuncAttributeMaxDynamicSharedMemorySize, SMEM_GEMM);

    prep_kernel     <<<5, 256>>>(W_edge, W_node, b_node, W_comb, b_comb, src);  // idx 0
    gemm_mma_kernel <<<1750, 256, SMEM_GEMM>>>(x, W_node, b_node);              // idx 1
    edge_kernel     <<<BB * E2C / 16, 256>>>(w_attn, src, dst, eidx, out);      // idx 2
    aggregate_kernel<<<BB * 125, 256>>>(dst, out);                              // idx 3 (profiled)
}